// round 1
// baseline (speedup 1.0000x reference)
#include <cuda_runtime.h>
#include <cstdint>

#define T_TOK 8192
#define HID   1024
#define NEXP  8
#define INTERN 2816
#define BM 128
#define BN 64
#define BK 32
#define MAXTILES 136
#define SLOT_CAP (MAXTILES*BM)   // 17408

// ---------------- device scratch (static: no allocations allowed) -------------
__device__ int   g_top_idx[T_TOK*2];
__device__ float g_top_w[T_TOK*2];
__device__ int   g_cnt[NEXP];
__device__ int   g_fill[NEXP];
__device__ int   g_seg_base[NEXP];
__device__ int   g_tile_expert[MAXTILES];
__device__ int   g_tile_slot0[MAXTILES];
__device__ int   g_slot_token[SLOT_CAP];
__device__ int   g_slot_of[T_TOK*2];
__device__ float g_inter[(size_t)SLOT_CAP*INTERN];  // ~196 MB
__device__ float g_odown[(size_t)SLOT_CAP*HID];     // ~71 MB

__device__ __forceinline__ unsigned f2tf(float f){
    unsigned u; asm("cvt.rna.tf32.f32 %0, %1;" : "=r"(u) : "f"(f)); return u;
}

#define MMA_TF32(c,a,b) \
  asm volatile("mma.sync.aligned.m16n8k8.row.col.f32.tf32.tf32.f32 " \
               "{%0,%1,%2,%3},{%4,%5,%6,%7},{%8,%9},{%0,%1,%2,%3};" \
               : "+f"((c)[0]),"+f"((c)[1]),"+f"((c)[2]),"+f"((c)[3]) \
               : "r"((a)[0]),"r"((a)[1]),"r"((a)[2]),"r"((a)[3]), \
                 "r"((b)[0]),"r"((b)[1]))

// ---------------- kernel 0: init counters / worklist -------------------------
__global__ void k_init(){
    int i = blockIdx.x*blockDim.x + threadIdx.x;
    if (i < SLOT_CAP) g_slot_token[i] = -1;
    if (i < NEXP) { g_cnt[i] = 0; g_fill[i] = 0; }
    if (i < MAXTILES) g_tile_expert[i] = -1;
}

// ---------------- kernel 1: router (exact fp32) ------------------------------
__global__ void k_router(const float* __restrict__ x, const float* __restrict__ rw){
    int warp = (blockIdx.x*blockDim.x + threadIdx.x) >> 5;
    int lane = threadIdx.x & 31;
    if (warp >= T_TOK) return;
    const float* xr = x + (size_t)warp*HID;
    float acc[NEXP];
    #pragma unroll
    for (int e=0;e<NEXP;e++) acc[e]=0.f;
    for (int j=lane; j<HID; j+=32){
        float v = xr[j];
        const float* r = rw + j*NEXP;
        #pragma unroll
        for (int e=0;e<NEXP;e++) acc[e] += v*r[e];
    }
    #pragma unroll
    for (int o=16;o>0;o>>=1)
        #pragma unroll
        for (int e=0;e<NEXP;e++) acc[e] += __shfl_down_sync(0xffffffffu, acc[e], o);
    if (lane==0){
        int i0=0; float l0=acc[0];
        #pragma unroll
        for (int e=1;e<NEXP;e++) if (acc[e]>l0){ l0=acc[e]; i0=e; }
        int i1=-1; float l1=-1e30f;
        #pragma unroll
        for (int e=0;e<NEXP;e++) if (e!=i0 && acc[e]>l1){ l1=acc[e]; i1=e; }
        // renormalized top-2 softmax == pairwise sigmoid
        float w0 = 1.f/(1.f + expf(l1 - l0));
        g_top_idx[warp*2+0]=i0; g_top_idx[warp*2+1]=i1;
        g_top_w[warp*2+0]=w0;   g_top_w[warp*2+1]=1.f-w0;
        atomicAdd(&g_cnt[i0],1); atomicAdd(&g_cnt[i1],1);
    }
}

// ---------------- kernel 2: scan -> padded segments + tile worklist ----------
__global__ void k_scan(){
    if (threadIdx.x!=0 || blockIdx.x!=0) return;
    int base=0, tile=0;
    for (int e=0;e<NEXP;e++){
        g_seg_base[e]=base;
        int c=g_cnt[e];
        int nt=(c+BM-1)/BM;
        for (int j=0;j<nt;j++){ g_tile_expert[tile]=e; g_tile_slot0[tile]=base+j*BM; tile++; }
        base += nt*BM;
    }
}

// ---------------- kernel 3: scatter tokens into slots -------------------------
__global__ void k_scatter(){
    int t = blockIdx.x*blockDim.x + threadIdx.x;
    if (t>=T_TOK) return;
    #pragma unroll
    for (int k=0;k<2;k++){
        int e = g_top_idx[t*2+k];
        int pos = atomicAdd(&g_fill[e],1);
        int slot = g_seg_base[e]+pos;
        g_slot_token[slot]=t;
        g_slot_of[t*2+k]=slot;
    }
}

// ---------------- kernel 4: grouped GEMM1 (gate+up fused, SwiGLU epilogue) ----
__global__ __launch_bounds__(256) void k_gemm1(const float* __restrict__ x,
                                               const float* __restrict__ wg,
                                               const float* __restrict__ wu){
    __shared__ float As[BM][36];
    __shared__ float Bg[BK][72];
    __shared__ float Bu[BK][72];

    int e = g_tile_expert[blockIdx.x];
    if (e<0) return;
    int slot0 = g_tile_slot0[blockIdx.x];
    int n0 = blockIdx.y*BN;
    int tid = threadIdx.x, lane = tid&31, warp = tid>>5;
    int wm = warp>>1, wn = warp&1;
    int g = lane>>2, tg = lane&3;

    // A staging: 2 threads per row, 16 floats each
    int arow = tid>>1;
    int acol0 = (tid&1)*16;
    int tok = g_slot_token[slot0+arow];
    const float* aptr = (tok>=0) ? (x + (size_t)tok*HID) : nullptr;

    // B staging: 8 threads per row, 8 floats each (2 float4)
    int brow = tid>>3;
    int bc0  = (tid&7)*8;
    const float* bgp = wg + (size_t)e*HID*INTERN;
    const float* bup = wu + (size_t)e*HID*INTERN;

    float cg[2][4][4], cu[2][4][4];
    #pragma unroll
    for (int i=0;i<2;i++)
        #pragma unroll
        for (int j=0;j<4;j++)
            #pragma unroll
            for (int r=0;r<4;r++){ cg[i][j][r]=0.f; cu[i][j][r]=0.f; }

    for (int k0=0;k0<HID;k0+=BK){
        #pragma unroll
        for (int i=0;i<4;i++){
            float4 v = make_float4(0.f,0.f,0.f,0.f);
            if (aptr) v = *(const float4*)(aptr + k0 + acol0 + i*4);
            unsigned* d = (unsigned*)&As[arow][acol0+i*4];
            d[0]=f2tf(v.x); d[1]=f2tf(v.y); d[2]=f2tf(v.z); d[3]=f2tf(v.w);
        }
        #pragma unroll
        for (int j=0;j<2;j++){
            size_t off = (size_t)(k0+brow)*INTERN + n0 + bc0 + j*4;
            float4 vg = *(const float4*)(bgp + off);
            float4 vu = *(const float4*)(bup + off);
            unsigned* dg = (unsigned*)&Bg[brow][bc0+j*4];
            dg[0]=f2tf(vg.x); dg[1]=f2tf(vg.y); dg[2]=f2tf(vg.z); dg[3]=f2tf(vg.w);
            unsigned* du = (unsigned*)&Bu[brow][bc0+j*4];
            du[0]=f2tf(vu.x); du[1]=f2tf(vu.y); du[2]=f2tf(vu.z); du[3]=f2tf(vu.w);
        }
        __syncthreads();
        #pragma unroll
        for (int kk=0;kk<4;kk++){
            int kb = kk*8;
            unsigned a[2][4];
            #pragma unroll
            for (int mi=0;mi<2;mi++){
                int r0 = wm*32 + mi*16;
                a[mi][0] = *(unsigned*)&As[r0+g  ][kb+tg  ];
                a[mi][1] = *(unsigned*)&As[r0+g+8][kb+tg  ];
                a[mi][2] = *(unsigned*)&As[r0+g  ][kb+tg+4];
                a[mi][3] = *(unsigned*)&As[r0+g+8][kb+tg+4];
            }
            unsigned bgf[4][2], buf[4][2];
            #pragma unroll
            for (int ni=0;ni<4;ni++){
                int c0 = wn*32 + ni*8 + g;
                bgf[ni][0] = *(unsigned*)&Bg[kb+tg  ][c0];
                bgf[ni][1] = *(unsigned*)&Bg[kb+tg+4][c0];
                buf[ni][0] = *(unsigned*)&Bu[kb+tg  ][c0];
                buf[ni][1] = *(unsigned*)&Bu[kb+tg+4][c0];
            }
            #pragma unroll
            for (int mi=0;mi<2;mi++)
                #pragma unroll
                for (int ni=0;ni<4;ni++){
                    MMA_TF32(cg[mi][ni], a[mi], bgf[ni]);
                    MMA_TF32(cu[mi][ni], a[mi], buf[ni]);
                }
        }
        __syncthreads();
    }
    // SwiGLU epilogue -> g_inter (padded rows compute exact zeros)
    #pragma unroll
    for (int mi=0;mi<2;mi++)
        #pragma unroll
        for (int ni=0;ni<4;ni++)
            #pragma unroll
            for (int r=0;r<4;r++){
                int row = wm*32 + mi*16 + g + ((r>>1)?8:0);
                int col = wn*32 + ni*8 + tg*2 + (r&1);
                float gv = cg[mi][ni][r], uv = cu[mi][ni][r];
                float val = uv * (gv / (1.f + expf(-gv)));
                g_inter[(size_t)(slot0+row)*INTERN + n0 + col] = val;
            }
}

// ---------------- kernel 5: grouped GEMM2 (down proj) -------------------------
__global__ __launch_bounds__(256) void k_gemm2(const float* __restrict__ wd){
    __shared__ float As[BM][36];
    __shared__ float Bs[BK][72];

    int e = g_tile_expert[blockIdx.x];
    if (e<0) return;
    int slot0 = g_tile_slot0[blockIdx.x];
    int n0 = blockIdx.y*BN;
    int tid = threadIdx.x, lane = tid&31, warp = tid>>5;
    int wm = warp>>1, wn = warp&1;
    int g = lane>>2, tg = lane&3;

    int arow = tid>>1;
    int acol0 = (tid&1)*16;
    const float* aptr = g_inter + (size_t)(slot0+arow)*INTERN;

    int brow = tid>>3;
    int bc0  = (tid&7)*8;
    const float* bdp = wd + (size_t)e*INTERN*HID;

    float cc[2][4][4];
    #pragma unroll
    for (int i=0;i<2;i++)
        #pragma unroll
        for (int j=0;j<4;j++)
            #pragma unroll
            for (int r=0;r<4;r++) cc[i][j][r]=0.f;

    for (int k0=0;k0<INTERN;k0+=BK){
        #pragma unroll
        for (int i=0;i<4;i++){
            float4 v = *(const float4*)(aptr + k0 + acol0 + i*4);
            unsigned* d = (unsigned*)&As[arow][acol0+i*4];
            d[0]=f2tf(v.x); d[1]=f2tf(v.y); d[2]=f2tf(v.z); d[3]=f2tf(v.w);
        }
        #pragma unroll
        for (int j=0;j<2;j++){
            size_t off = (size_t)(k0+brow)*HID + n0 + bc0 + j*4;
            float4 vb = *(const float4*)(bdp + off);
            unsigned* db = (unsigned*)&Bs[brow][bc0+j*4];
            db[0]=f2tf(vb.x); db[1]=f2tf(vb.y); db[2]=f2tf(vb.z); db[3]=f2tf(vb.w);
        }
        __syncthreads();
        #pragma unroll
        for (int kk=0;kk<4;kk++){
            int kb = kk*8;
            unsigned a[2][4];
            #pragma unroll
            for (int mi=0;mi<2;mi++){
                int r0 = wm*32 + mi*16;
                a[mi][0] = *(unsigned*)&As[r0+g  ][kb+tg  ];
                a[mi][1] = *(unsigned*)&As[r0+g+8][kb+tg  ];
                a[mi][2] = *(unsigned*)&As[r0+g  ][kb+tg+4];
                a[mi][3] = *(unsigned*)&As[r0+g+8][kb+tg+4];
            }
            unsigned bf[4][2];
            #pragma unroll
            for (int ni=0;ni<4;ni++){
                int c0 = wn*32 + ni*8 + g;
                bf[ni][0] = *(unsigned*)&Bs[kb+tg  ][c0];
                bf[ni][1] = *(unsigned*)&Bs[kb+tg+4][c0];
            }
            #pragma unroll
            for (int mi=0;mi<2;mi++)
                #pragma unroll
                for (int ni=0;ni<4;ni++)
                    MMA_TF32(cc[mi][ni], a[mi], bf[ni]);
        }
        __syncthreads();
    }
    #pragma unroll
    for (int mi=0;mi<2;mi++)
        #pragma unroll
        for (int ni=0;ni<4;ni++)
            #pragma unroll
            for (int r=0;r<4;r++){
                int row = wm*32 + mi*16 + g + ((r>>1)?8:0);
                int col = wn*32 + ni*8 + tg*2 + (r&1);
                g_odown[(size_t)(slot0+row)*HID + n0 + col] = cc[mi][ni][r];
            }
}

// ---------------- kernel 6: deterministic combine -----------------------------
__global__ void k_combine(float* __restrict__ out){
    int i = blockIdx.x*blockDim.x + threadIdx.x;   // over T*H/4 float4s
    if (i >= T_TOK*HID/4) return;
    int t = i / (HID/4);
    int q = i % (HID/4);
    int s0 = g_slot_of[t*2+0], s1 = g_slot_of[t*2+1];
    float w0 = g_top_w[t*2+0], w1 = g_top_w[t*2+1];
    float4 a = *(const float4*)(g_odown + (size_t)s0*HID + q*4);
    float4 b = *(const float4*)(g_odown + (size_t)s1*HID + q*4);
    float4 o;
    o.x = w0*a.x + w1*b.x;
    o.y = w0*a.y + w1*b.y;
    o.z = w0*a.z + w1*b.z;
    o.w = w0*a.w + w1*b.w;
    *(float4*)(out + (size_t)t*HID + q*4) = o;
}

// ---------------- launch ------------------------------------------------------
extern "C" void kernel_launch(void* const* d_in, const int* in_sizes, int n_in,
                              void* d_out, int out_size){
    const float* x  = (const float*)d_in[0];   // hidden_states (4,2048,1024)
    const float* rw = (const float*)d_in[1];   // router_w (1024,8)
    const float* wg = (const float*)d_in[2];   // w_gate (8,1024,2816)
    const float* wu = (const float*)d_in[3];   // w_up   (8,1024,2816)
    const float* wd = (const float*)d_in[4];   // w_down (8,2816,1024)
    float* out = (float*)d_out;

    k_init<<<(SLOT_CAP+255)/256, 256>>>();
    k_router<<<T_TOK/8, 256>>>(x, rw);
    k_scan<<<1, 32>>>();
    k_scatter<<<(T_TOK+255)/256, 256>>>();
    k_gemm1<<<dim3(MAXTILES, INTERN/BN), 256>>>(x, wg, wu);
    k_gemm2<<<dim3(MAXTILES, HID/BN), 256>>>(wd);
    k_combine<<<(T_TOK*HID/4+255)/256, 256>>>(out);
}

// round 2
// speedup vs baseline: 1.0424x; 1.0424x over previous
#include <cuda_runtime.h>
#include <cstdint>

#define T_TOK 8192
#define HID   1024
#define NEXP  8
#define INTERN 2816
#define BM 128
#define BN 64
#define BK 32
#define MAXTILES 136
#define SLOT_CAP (MAXTILES*BM)   // 17408

// ---------------- device scratch (static: no allocations allowed) -------------
__device__ int   g_top_idx[T_TOK*2];
__device__ float g_top_w[T_TOK*2];
__device__ int   g_cnt[NEXP];
__device__ int   g_fill[NEXP];
__device__ int   g_seg_base[NEXP];
__device__ int   g_tile_expert[MAXTILES];
__device__ int   g_tile_slot0[MAXTILES];
__device__ int   g_slot_token[SLOT_CAP];
__device__ int   g_slot_of[T_TOK*2];
__device__ float g_inter[(size_t)SLOT_CAP*INTERN];  // ~196 MB (stored pre-rounded to tf32)
__device__ float g_odown[(size_t)SLOT_CAP*HID];     // ~71 MB

__device__ __forceinline__ unsigned f2tf(float f){
    unsigned u; asm("cvt.rna.tf32.f32 %0, %1;" : "=r"(u) : "f"(f)); return u;
}

#define MMA_TF32(c,a,b) \
  asm volatile("mma.sync.aligned.m16n8k8.row.col.f32.tf32.tf32.f32 " \
               "{%0,%1,%2,%3},{%4,%5,%6,%7},{%8,%9},{%0,%1,%2,%3};" \
               : "+f"((c)[0]),"+f"((c)[1]),"+f"((c)[2]),"+f"((c)[3]) \
               : "r"((a)[0]),"r"((a)[1]),"r"((a)[2]),"r"((a)[3]), \
                 "r"((b)[0]),"r"((b)[1]))

__device__ __forceinline__ void cp16(unsigned dst, const void* src, int sz){
    asm volatile("cp.async.cg.shared.global [%0], [%1], 16, %2;\n"
                 :: "r"(dst), "l"(src), "r"(sz));
}
#define CP_COMMIT asm volatile("cp.async.commit_group;\n" ::: "memory")
#define CP_WAIT1  asm volatile("cp.async.wait_group 1;\n" ::: "memory")
#define CP_WAIT0  asm volatile("cp.async.wait_group 0;\n" ::: "memory")

// ---------------- kernel 0: init counters / worklist -------------------------
__global__ void k_init(){
    int i = blockIdx.x*blockDim.x + threadIdx.x;
    if (i < SLOT_CAP) g_slot_token[i] = -1;
    if (i < NEXP) { g_cnt[i] = 0; g_fill[i] = 0; }
    if (i < MAXTILES) g_tile_expert[i] = -1;
}

// ---------------- kernel 1: router (exact fp32) ------------------------------
__global__ void k_router(const float* __restrict__ x, const float* __restrict__ rw){
    int warp = (blockIdx.x*blockDim.x + threadIdx.x) >> 5;
    int lane = threadIdx.x & 31;
    if (warp >= T_TOK) return;
    const float* xr = x + (size_t)warp*HID;
    float acc[NEXP];
    #pragma unroll
    for (int e=0;e<NEXP;e++) acc[e]=0.f;
    for (int j=lane; j<HID; j+=32){
        float v = xr[j];
        const float* r = rw + j*NEXP;
        #pragma unroll
        for (int e=0;e<NEXP;e++) acc[e] += v*r[e];
    }
    #pragma unroll
    for (int o=16;o>0;o>>=1)
        #pragma unroll
        for (int e=0;e<NEXP;e++) acc[e] += __shfl_down_sync(0xffffffffu, acc[e], o);
    if (lane==0){
        int i0=0; float l0=acc[0];
        #pragma unroll
        for (int e=1;e<NEXP;e++) if (acc[e]>l0){ l0=acc[e]; i0=e; }
        int i1=-1; float l1=-1e30f;
        #pragma unroll
        for (int e=0;e<NEXP;e++) if (e!=i0 && acc[e]>l1){ l1=acc[e]; i1=e; }
        float w0 = 1.f/(1.f + expf(l1 - l0));
        g_top_idx[warp*2+0]=i0; g_top_idx[warp*2+1]=i1;
        g_top_w[warp*2+0]=w0;   g_top_w[warp*2+1]=1.f-w0;
        atomicAdd(&g_cnt[i0],1); atomicAdd(&g_cnt[i1],1);
    }
}

// ---------------- kernel 2: scan -> padded segments + tile worklist ----------
__global__ void k_scan(){
    if (threadIdx.x!=0 || blockIdx.x!=0) return;
    int base=0, tile=0;
    for (int e=0;e<NEXP;e++){
        g_seg_base[e]=base;
        int c=g_cnt[e];
        int nt=(c+BM-1)/BM;
        for (int j=0;j<nt;j++){ g_tile_expert[tile]=e; g_tile_slot0[tile]=base+j*BM; tile++; }
        base += nt*BM;
    }
}

// ---------------- kernel 3: scatter tokens into slots -------------------------
__global__ void k_scatter(){
    int t = blockIdx.x*blockDim.x + threadIdx.x;
    if (t>=T_TOK) return;
    #pragma unroll
    for (int k=0;k<2;k++){
        int e = g_top_idx[t*2+k];
        int pos = atomicAdd(&g_fill[e],1);
        int slot = g_seg_base[e]+pos;
        g_slot_token[slot]=t;
        g_slot_of[t*2+k]=slot;
    }
}

// smem float offsets (gemm1): As 2*128*36=9216 | Bg 2*32*72=4608 | Bu 4608  => 18432 floats
#define G1_A_OFF  0
#define G1_BG_OFF 9216
#define G1_BU_OFF 13824
#define G1_SMEM_BYTES (18432*4)

// ---------------- kernel 4: grouped GEMM1 (gate+up fused, SwiGLU epilogue) ----
__global__ __launch_bounds__(256,2) void k_gemm1(const float* __restrict__ x,
                                                 const float* __restrict__ wg,
                                                 const float* __restrict__ wu){
    extern __shared__ float sm[];
    int e = g_tile_expert[blockIdx.x];
    if (e<0) return;
    int slot0 = g_tile_slot0[blockIdx.x];
    int n0 = blockIdx.y*BN;
    int tid = threadIdx.x, lane = tid&31, warp = tid>>5;
    int wm = warp>>1, wn = warp&1;
    int g = lane>>2, tg = lane&3;
    unsigned smb = (unsigned)__cvta_generic_to_shared(sm);

    // A staging: 2 threads per row, 16 floats (4 cp.async) each
    int arow = tid>>1;
    int acol0 = (tid&1)*16;
    int tok = g_slot_token[slot0+arow];
    const float* aptr = x + (size_t)((tok>=0)?tok:0)*HID;
    int asz = (tok>=0)?16:0;

    // B staging: 8 threads per row, 8 floats (2 cp.async) each, per matrix
    int brow = tid>>3;
    int bc0  = (tid&7)*8;
    const float* bgp = wg + (size_t)e*HID*INTERN + n0;
    const float* bup = wu + (size_t)e*HID*INTERN + n0;

    float cg[2][4][4], cu[2][4][4];
    #pragma unroll
    for (int i=0;i<2;i++)
        #pragma unroll
        for (int j=0;j<4;j++)
            #pragma unroll
            for (int r=0;r<4;r++){ cg[i][j][r]=0.f; cu[i][j][r]=0.f; }

    auto issue = [&](int s, int k0){
        unsigned ad = smb + (G1_A_OFF + s*4608 + arow*36 + acol0)*4;
        #pragma unroll
        for (int i=0;i<4;i++) cp16(ad + i*16, aptr + k0 + acol0 + i*4, asz);
        unsigned gd = smb + (G1_BG_OFF + s*2304 + brow*72 + bc0)*4;
        unsigned ud = smb + (G1_BU_OFF + s*2304 + brow*72 + bc0)*4;
        size_t boff = (size_t)(k0+brow)*INTERN + bc0;
        #pragma unroll
        for (int j=0;j<2;j++){
            cp16(gd + j*16, bgp + boff + j*4, 16);
            cp16(ud + j*16, bup + boff + j*4, 16);
        }
        CP_COMMIT;
    };

    issue(0, 0);
    const int NT = HID/BK;  // 32
    for (int kt=0; kt<NT; kt++){
        int s = kt&1;
        bool more = (kt+1 < NT);
        if (more) issue(s^1, (kt+1)*BK);
        if (more) CP_WAIT1; else CP_WAIT0;
        __syncthreads();
        const float* AsS = sm + G1_A_OFF  + s*4608;
        const float* BgS = sm + G1_BG_OFF + s*2304;
        const float* BuS = sm + G1_BU_OFF + s*2304;
        #pragma unroll
        for (int kk=0;kk<4;kk++){
            int kb = kk*8;
            unsigned a[2][4];
            #pragma unroll
            for (int mi=0;mi<2;mi++){
                int r0 = wm*32 + mi*16;
                a[mi][0] = f2tf(AsS[(r0+g  )*36 + kb+tg  ]);
                a[mi][1] = f2tf(AsS[(r0+g+8)*36 + kb+tg  ]);
                a[mi][2] = f2tf(AsS[(r0+g  )*36 + kb+tg+4]);
                a[mi][3] = f2tf(AsS[(r0+g+8)*36 + kb+tg+4]);
            }
            unsigned bgf[4][2], buf[4][2];
            #pragma unroll
            for (int ni=0;ni<4;ni++){
                int c0 = wn*32 + ni*8 + g;
                bgf[ni][0] = f2tf(BgS[(kb+tg  )*72 + c0]);
                bgf[ni][1] = f2tf(BgS[(kb+tg+4)*72 + c0]);
                buf[ni][0] = f2tf(BuS[(kb+tg  )*72 + c0]);
                buf[ni][1] = f2tf(BuS[(kb+tg+4)*72 + c0]);
            }
            #pragma unroll
            for (int mi=0;mi<2;mi++)
                #pragma unroll
                for (int ni=0;ni<4;ni++){
                    MMA_TF32(cg[mi][ni], a[mi], bgf[ni]);
                    MMA_TF32(cu[mi][ni], a[mi], buf[ni]);
                }
        }
        __syncthreads();
    }
    // SwiGLU epilogue -> g_inter, pre-rounded to tf32 so GEMM2 skips cvt on A
    #pragma unroll
    for (int mi=0;mi<2;mi++)
        #pragma unroll
        for (int ni=0;ni<4;ni++)
            #pragma unroll
            for (int r=0;r<4;r++){
                int row = wm*32 + mi*16 + g + ((r>>1)?8:0);
                int col = wn*32 + ni*8 + tg*2 + (r&1);
                float gv = cg[mi][ni][r], uv = cu[mi][ni][r];
                float val = uv * (gv / (1.f + expf(-gv)));
                g_inter[(size_t)(slot0+row)*INTERN + n0 + col] = __uint_as_float(f2tf(val));
            }
}

// smem float offsets (gemm2): As 2*128*36=9216 | Bs 2*32*72=4608 => 13824 floats
#define G2_A_OFF 0
#define G2_B_OFF 9216
#define G2_SMEM_BYTES (13824*4)

// ---------------- kernel 5: grouped GEMM2 (down proj) -------------------------
__global__ __launch_bounds__(256,2) void k_gemm2(const float* __restrict__ wd){
    extern __shared__ float sm[];
    int e = g_tile_expert[blockIdx.x];
    if (e<0) return;
    int slot0 = g_tile_slot0[blockIdx.x];
    int n0 = blockIdx.y*BN;
    int tid = threadIdx.x, lane = tid&31, warp = tid>>5;
    int wm = warp>>1, wn = warp&1;
    int g = lane>>2, tg = lane&3;
    unsigned smb = (unsigned)__cvta_generic_to_shared(sm);

    int arow = tid>>1;
    int acol0 = (tid&1)*16;
    const float* aptr = g_inter + (size_t)(slot0+arow)*INTERN;

    int brow = tid>>3;
    int bc0  = (tid&7)*8;
    const float* bdp = wd + (size_t)e*INTERN*HID + n0;

    float cc[2][4][4];
    #pragma unroll
    for (int i=0;i<2;i++)
        #pragma unroll
        for (int j=0;j<4;j++)
            #pragma unroll
            for (int r=0;r<4;r++) cc[i][j][r]=0.f;

    auto issue = [&](int s, int k0){
        unsigned ad = smb + (G2_A_OFF + s*4608 + arow*36 + acol0)*4;
        #pragma unroll
        for (int i=0;i<4;i++) cp16(ad + i*16, aptr + k0 + acol0 + i*4, 16);
        unsigned bd = smb + (G2_B_OFF + s*2304 + brow*72 + bc0)*4;
        size_t boff = (size_t)(k0+brow)*HID + bc0;
        #pragma unroll
        for (int j=0;j<2;j++) cp16(bd + j*16, bdp + boff + j*4, 16);
        CP_COMMIT;
    };

    issue(0, 0);
    const int NT = INTERN/BK;  // 88
    for (int kt=0; kt<NT; kt++){
        int s = kt&1;
        bool more = (kt+1 < NT);
        if (more) issue(s^1, (kt+1)*BK);
        if (more) CP_WAIT1; else CP_WAIT0;
        __syncthreads();
        const float* AsS = sm + G2_A_OFF + s*4608;
        const float* BsS = sm + G2_B_OFF + s*2304;
        #pragma unroll
        for (int kk=0;kk<4;kk++){
            int kb = kk*8;
            unsigned a[2][4];
            #pragma unroll
            for (int mi=0;mi<2;mi++){
                int r0 = wm*32 + mi*16;
                // g_inter already tf32-rounded: raw bit loads, no cvt
                a[mi][0] = *(const unsigned*)&AsS[(r0+g  )*36 + kb+tg  ];
                a[mi][1] = *(const unsigned*)&AsS[(r0+g+8)*36 + kb+tg  ];
                a[mi][2] = *(const unsigned*)&AsS[(r0+g  )*36 + kb+tg+4];
                a[mi][3] = *(const unsigned*)&AsS[(r0+g+8)*36 + kb+tg+4];
            }
            unsigned bf[4][2];
            #pragma unroll
            for (int ni=0;ni<4;ni++){
                int c0 = wn*32 + ni*8 + g;
                bf[ni][0] = f2tf(BsS[(kb+tg  )*72 + c0]);
                bf[ni][1] = f2tf(BsS[(kb+tg+4)*72 + c0]);
            }
            #pragma unroll
            for (int mi=0;mi<2;mi++)
                #pragma unroll
                for (int ni=0;ni<4;ni++)
                    MMA_TF32(cc[mi][ni], a[mi], bf[ni]);
        }
        __syncthreads();
    }
    #pragma unroll
    for (int mi=0;mi<2;mi++)
        #pragma unroll
        for (int ni=0;ni<4;ni++)
            #pragma unroll
            for (int r=0;r<4;r++){
                int row = wm*32 + mi*16 + g + ((r>>1)?8:0);
                int col = wn*32 + ni*8 + tg*2 + (r&1);
                g_odown[(size_t)(slot0+row)*HID + n0 + col] = cc[mi][ni][r];
            }
}

// ---------------- kernel 6: deterministic combine -----------------------------
__global__ void k_combine(float* __restrict__ out){
    int i = blockIdx.x*blockDim.x + threadIdx.x;   // over T*H/4 float4s
    if (i >= T_TOK*HID/4) return;
    int t = i / (HID/4);
    int q = i % (HID/4);
    int s0 = g_slot_of[t*2+0], s1 = g_slot_of[t*2+1];
    float w0 = g_top_w[t*2+0], w1 = g_top_w[t*2+1];
    float4 a = *(const float4*)(g_odown + (size_t)s0*HID + q*4);
    float4 b = *(const float4*)(g_odown + (size_t)s1*HID + q*4);
    float4 o;
    o.x = w0*a.x + w1*b.x;
    o.y = w0*a.y + w1*b.y;
    o.z = w0*a.z + w1*b.z;
    o.w = w0*a.w + w1*b.w;
    *(float4*)(out + (size_t)t*HID + q*4) = o;
}

// ---------------- launch ------------------------------------------------------
extern "C" void kernel_launch(void* const* d_in, const int* in_sizes, int n_in,
                              void* d_out, int out_size){
    const float* x  = (const float*)d_in[0];   // hidden_states (4,2048,1024)
    const float* rw = (const float*)d_in[1];   // router_w (1024,8)
    const float* wg = (const float*)d_in[2];   // w_gate (8,1024,2816)
    const float* wu = (const float*)d_in[3];   // w_up   (8,1024,2816)
    const float* wd = (const float*)d_in[4];   // w_down (8,2816,1024)
    float* out = (float*)d_out;

    cudaFuncSetAttribute(k_gemm1, cudaFuncAttributeMaxDynamicSharedMemorySize, G1_SMEM_BYTES);
    cudaFuncSetAttribute(k_gemm2, cudaFuncAttributeMaxDynamicSharedMemorySize, G2_SMEM_BYTES);

    k_init<<<(SLOT_CAP+255)/256, 256>>>();
    k_router<<<T_TOK/8, 256>>>(x, rw);
    k_scan<<<1, 32>>>();
    k_scatter<<<(T_TOK+255)/256, 256>>>();
    k_gemm1<<<dim3(MAXTILES, INTERN/BN), 256, G1_SMEM_BYTES>>>(x, wg, wu);
    k_gemm2<<<dim3(MAXTILES, HID/BN), 256, G2_SMEM_BYTES>>>(wd);
    k_combine<<<(T_TOK*HID/4+255)/256, 256>>>(out);
}

// round 4
// speedup vs baseline: 1.8402x; 1.7654x over previous
#include <cuda_runtime.h>
#include <cuda_fp16.h>
#include <cstdint>

#define T_TOK 8192
#define HID   1024
#define NEXP  8
#define INTERN 2816
#define BM 128
#define BK 32                  // k halves per stage
#define MAXTILES 136
#define SLOT_CAP (MAXTILES*BM) // 17408
#define PITCH 40               // smem row pitch in halves (80B: 16B-aligned, conflict-free)

// ---------------- device scratch -------------------------------------------
__device__ int    g_top_idx[T_TOK*2];
__device__ float  g_top_w[T_TOK*2];
__device__ int    g_cnt[NEXP];
__device__ int    g_fill[NEXP];
__device__ int    g_seg_base[NEXP];
__device__ int    g_tile_expert[MAXTILES];
__device__ int    g_tile_slot0[MAXTILES];
__device__ int    g_slot_token[SLOT_CAP];
__device__ int    g_slot_of[T_TOK*2];
__device__ __half g_xh[(size_t)T_TOK*HID];                 // x in fp16
__device__ __half g_wgT[(size_t)NEXP*INTERN*HID];          // gate  [e][n=I][k=H]
__device__ __half g_wuT[(size_t)NEXP*INTERN*HID];          // up    [e][n=I][k=H]
__device__ __half g_wdT[(size_t)NEXP*HID*INTERN];          // down  [e][n=H][k=I]
__device__ __half g_interh[(size_t)SLOT_CAP*INTERN];       // swiglu out (fp16)
__device__ float  g_odown[(size_t)SLOT_CAP*HID];

// ---------------- helpers ----------------------------------------------------
__device__ __forceinline__ void cp16(uint32_t dst, const void* src, int sz){
    asm volatile("cp.async.cg.shared.global [%0], [%1], 16, %2;\n" :: "r"(dst), "l"(src), "r"(sz));
}
#define CP_COMMIT asm volatile("cp.async.commit_group;\n" ::: "memory")
#define CP_WAIT1  asm volatile("cp.async.wait_group 1;\n" ::: "memory")
#define CP_WAIT0  asm volatile("cp.async.wait_group 0;\n" ::: "memory")

#define MMA_F16(c,a,b) \
  asm volatile("mma.sync.aligned.m16n8k16.row.col.f32.f16.f16.f32 " \
               "{%0,%1,%2,%3},{%4,%5,%6,%7},{%8,%9},{%0,%1,%2,%3};" \
               : "+f"((c)[0]),"+f"((c)[1]),"+f"((c)[2]),"+f"((c)[3]) \
               : "r"((a)[0]),"r"((a)[1]),"r"((a)[2]),"r"((a)[3]), \
                 "r"((b)[0]),"r"((b)[1]))

__device__ __forceinline__ uint32_t s2u(const void* p){
    uint32_t a;
    asm("{ .reg .u64 t; cvta.to.shared.u64 t, %1; cvt.u32.u64 %0, t; }" : "=r"(a) : "l"(p));
    return a;
}

// ---------------- kernel 0: init -------------------------------------------
__global__ void k_init(){
    int i = blockIdx.x*blockDim.x + threadIdx.x;
    if (i < SLOT_CAP) g_slot_token[i] = -1;
    if (i < NEXP) { g_cnt[i] = 0; g_fill[i] = 0; }
    if (i < MAXTILES) g_tile_expert[i] = -1;
}

// ---------------- x -> fp16 --------------------------------------------------
__global__ void k_xhalf(const float* __restrict__ x){
    int i = blockIdx.x*blockDim.x + threadIdx.x;
    if (i < T_TOK*HID/2){
        float2 v = ((const float2*)x)[i];
        ((__half2*)g_xh)[i] = __floats2half2_rn(v.x, v.y);
    }
}

// ---------------- weight transpose+convert: [e][K][N] f32 -> [e][N][K] f16 ---
__global__ void k_transpose(const float* __restrict__ in, __half* __restrict__ out,
                            int K, int N){
    __shared__ float t[32][33];
    int e = blockIdx.z;
    const float* src = in + (size_t)e*K*N;
    __half* dst = out + (size_t)e*N*K;
    int x = blockIdx.x*32, y = blockIdx.y*32;
    int tx = threadIdx.x, ty = threadIdx.y;
    #pragma unroll
    for (int j=0;j<4;j++)
        t[ty+8*j][tx] = src[(size_t)(y+ty+8*j)*N + x+tx];
    __syncthreads();
    #pragma unroll
    for (int j=0;j<4;j++)
        dst[(size_t)(x+ty+8*j)*K + y+tx] = __float2half_rn(t[tx][ty+8*j]);
}

// ---------------- router (exact fp32) ----------------------------------------
__global__ void k_router(const float* __restrict__ x, const float* __restrict__ rw){
    int warp = (blockIdx.x*blockDim.x + threadIdx.x) >> 5;
    int lane = threadIdx.x & 31;
    if (warp >= T_TOK) return;
    const float* xr = x + (size_t)warp*HID;
    float acc[NEXP];
    #pragma unroll
    for (int e=0;e<NEXP;e++) acc[e]=0.f;
    for (int j=lane; j<HID; j+=32){
        float v = xr[j];
        const float* r = rw + j*NEXP;
        #pragma unroll
        for (int e=0;e<NEXP;e++) acc[e] += v*r[e];
    }
    #pragma unroll
    for (int o=16;o>0;o>>=1)
        #pragma unroll
        for (int e=0;e<NEXP;e++) acc[e] += __shfl_down_sync(0xffffffffu, acc[e], o);
    if (lane==0){
        int i0=0; float l0=acc[0];
        #pragma unroll
        for (int e=1;e<NEXP;e++) if (acc[e]>l0){ l0=acc[e]; i0=e; }
        int i1=-1; float l1=-1e30f;
        #pragma unroll
        for (int e=0;e<NEXP;e++) if (e!=i0 && acc[e]>l1){ l1=acc[e]; i1=e; }
        float w0 = 1.f/(1.f + expf(l1 - l0));
        g_top_idx[warp*2+0]=i0; g_top_idx[warp*2+1]=i1;
        g_top_w[warp*2+0]=w0;   g_top_w[warp*2+1]=1.f-w0;
        atomicAdd(&g_cnt[i0],1); atomicAdd(&g_cnt[i1],1);
    }
}

// ---------------- scan -------------------------------------------------------
__global__ void k_scan(){
    if (threadIdx.x!=0 || blockIdx.x!=0) return;
    int base=0, tile=0;
    for (int e=0;e<NEXP;e++){
        g_seg_base[e]=base;
        int c=g_cnt[e];
        int nt=(c+BM-1)/BM;
        for (int j=0;j<nt;j++){ g_tile_expert[tile]=e; g_tile_slot0[tile]=base+j*BM; tile++; }
        base += nt*BM;
    }
}

// ---------------- scatter ----------------------------------------------------
__global__ void k_scatter(){
    int t = blockIdx.x*blockDim.x + threadIdx.x;
    if (t>=T_TOK) return;
    #pragma unroll
    for (int k=0;k<2;k++){
        int e = g_top_idx[t*2+k];
        int pos = atomicAdd(&g_fill[e],1);
        int slot = g_seg_base[e]+pos;
        g_slot_token[slot]=t;
        g_slot_of[t*2+k]=slot;
    }
}

// ============ GEMM1: fp16 HMMA, gate+up fused, SwiGLU epilogue ===============
__global__ void __launch_bounds__(256,2) k_gemm1(){
    __shared__ __half As[2][BM*PITCH];      // 20 KB
    __shared__ __half Bs[2][128*PITCH];     // 20 KB (rows 0-63 gate, 64-127 up)

    int e = g_tile_expert[blockIdx.x];
    if (e<0) return;
    int slot0 = g_tile_slot0[blockIdx.x];
    int n0 = blockIdx.y*64;
    int tid=threadIdx.x, lane=tid&31, warp=tid>>5;
    int wm = warp>>1, wn = warp&1;
    int g = lane>>2, tg = lane&3;
    uint32_t sA = s2u(As), sB = s2u(Bs);

    // A staging: 2 threads/row, 32B each (2 cp16)
    int arow = tid>>1, ak = (tid&1)*16;    // halves
    int tok = g_slot_token[slot0+arow];
    const __half* asrc = g_xh + (size_t)((tok>=0)?tok:0)*HID + ak;
    int asz = (tok>=0)?16:0;
    // B staging: 2 threads/row over 128 rows; row<64 gate col n0+row, else up
    int brow = tid>>1, bk = (tid&1)*16;
    const __half* bsrc = ((brow<64)? g_wgT + (size_t)e*INTERN*HID + (size_t)(n0+brow)*HID
                                   : g_wuT + (size_t)e*INTERN*HID + (size_t)(n0+brow-64)*HID) + bk;

    float cg[2][4][4], cu[2][4][4];
    #pragma unroll
    for (int i=0;i<2;i++)
        #pragma unroll
        for (int j=0;j<4;j++)
            #pragma unroll
            for (int r=0;r<4;r++){ cg[i][j][r]=0.f; cu[i][j][r]=0.f; }

    auto stage = [&](int s, int k0){
        uint32_t ad = sA + (uint32_t)(s*BM*PITCH + arow*PITCH + ak)*2;
        cp16(ad,      asrc + k0,     asz);
        cp16(ad + 16, asrc + k0 + 8, asz);
        uint32_t bd = sB + (uint32_t)(s*128*PITCH + brow*PITCH + bk)*2;
        cp16(bd,      bsrc + k0,     16);
        cp16(bd + 16, bsrc + k0 + 8, 16);
        CP_COMMIT;
    };

    stage(0, 0);
    const int NT = HID/BK;   // 32
    for (int kt=0; kt<NT; kt++){
        int s = kt&1;
        if (kt+1 < NT){ stage(s^1, (kt+1)*BK); CP_WAIT1; } else CP_WAIT0;
        __syncthreads();
        const __half* A_ = As[s];
        const __half* B_ = Bs[s];
        #pragma unroll
        for (int ks=0; ks<2; ks++){
            int kb = ks*16;
            uint32_t a[2][4];
            #pragma unroll
            for (int mi=0;mi<2;mi++){
                int r0 = wm*32 + mi*16;
                a[mi][0] = *(const uint32_t*)&A_[(r0+g  )*PITCH + kb + 2*tg    ];
                a[mi][1] = *(const uint32_t*)&A_[(r0+g+8)*PITCH + kb + 2*tg    ];
                a[mi][2] = *(const uint32_t*)&A_[(r0+g  )*PITCH + kb + 2*tg + 8];
                a[mi][3] = *(const uint32_t*)&A_[(r0+g+8)*PITCH + kb + 2*tg + 8];
            }
            uint32_t bg[4][2], bu[4][2];
            #pragma unroll
            for (int ni=0;ni<4;ni++){
                int c0 = wn*32 + ni*8 + g;
                bg[ni][0] = *(const uint32_t*)&B_[(c0   )*PITCH + kb + 2*tg    ];
                bg[ni][1] = *(const uint32_t*)&B_[(c0   )*PITCH + kb + 2*tg + 8];
                bu[ni][0] = *(const uint32_t*)&B_[(c0+64)*PITCH + kb + 2*tg    ];
                bu[ni][1] = *(const uint32_t*)&B_[(c0+64)*PITCH + kb + 2*tg + 8];
            }
            #pragma unroll
            for (int mi=0;mi<2;mi++)
                #pragma unroll
                for (int ni=0;ni<4;ni++){
                    MMA_F16(cg[mi][ni], a[mi], bg[ni]);
                    MMA_F16(cu[mi][ni], a[mi], bu[ni]);
                }
        }
        __syncthreads();
    }
    // SwiGLU epilogue -> g_interh (fp16)
    #pragma unroll
    for (int mi=0;mi<2;mi++)
        #pragma unroll
        for (int ni=0;ni<4;ni++)
            #pragma unroll
            for (int rr=0;rr<2;rr++){
                int row = wm*32 + mi*16 + g + rr*8;
                int col = wn*32 + ni*8 + 2*tg;
                float g0 = cg[mi][ni][rr*2+0], u0 = cu[mi][ni][rr*2+0];
                float g1 = cg[mi][ni][rr*2+1], u1 = cu[mi][ni][rr*2+1];
                float v0 = u0 * (g0 / (1.f + expf(-g0)));
                float v1 = u1 * (g1 / (1.f + expf(-g1)));
                *(__half2*)(g_interh + (size_t)(slot0+row)*INTERN + n0 + col)
                    = __floats2half2_rn(v0, v1);
            }
}

// ============ GEMM2: fp16 HMMA, down proj ====================================
__global__ void __launch_bounds__(256,2) k_gemm2(){
    __shared__ __half As[2][BM*PITCH];      // 20 KB
    __shared__ __half Bs[2][64*PITCH];      // 10 KB

    int e = g_tile_expert[blockIdx.x];
    if (e<0) return;
    int slot0 = g_tile_slot0[blockIdx.x];
    int n0 = blockIdx.y*64;
    int tid=threadIdx.x, lane=tid&31, warp=tid>>5;
    int wm = warp>>1, wn = warp&1;
    int g = lane>>2, tg = lane&3;
    uint32_t sA = s2u(As), sB = s2u(Bs);

    int arow = tid>>1, ak = (tid&1)*16;
    const __half* asrc = g_interh + (size_t)(slot0+arow)*INTERN + ak;
    int brow = tid>>2, bk = (tid&3)*8;
    const __half* bsrc = g_wdT + (size_t)e*HID*INTERN + (size_t)(n0+brow)*INTERN + bk;

    float cc[2][4][4];
    #pragma unroll
    for (int i=0;i<2;i++)
        #pragma unroll
        for (int j=0;j<4;j++)
            #pragma unroll
            for (int r=0;r<4;r++) cc[i][j][r]=0.f;

    auto stage = [&](int s, int k0){
        uint32_t ad = sA + (uint32_t)(s*BM*PITCH + arow*PITCH + ak)*2;
        cp16(ad,      asrc + k0,     16);
        cp16(ad + 16, asrc + k0 + 8, 16);
        uint32_t bd = sB + (uint32_t)(s*64*PITCH + brow*PITCH + bk)*2;
        cp16(bd, bsrc + k0, 16);
        CP_COMMIT;
    };

    stage(0, 0);
    const int NT = INTERN/BK;   // 88
    for (int kt=0; kt<NT; kt++){
        int s = kt&1;
        if (kt+1 < NT){ stage(s^1, (kt+1)*BK); CP_WAIT1; } else CP_WAIT0;
        __syncthreads();
        const __half* A_ = As[s];
        const __half* B_ = Bs[s];
        #pragma unroll
        for (int ks=0; ks<2; ks++){
            int kb = ks*16;
            uint32_t a[2][4];
            #pragma unroll
            for (int mi=0;mi<2;mi++){
                int r0 = wm*32 + mi*16;
                a[mi][0] = *(const uint32_t*)&A_[(r0+g  )*PITCH + kb + 2*tg    ];
                a[mi][1] = *(const uint32_t*)&A_[(r0+g+8)*PITCH + kb + 2*tg    ];
                a[mi][2] = *(const uint32_t*)&A_[(r0+g  )*PITCH + kb + 2*tg + 8];
                a[mi][3] = *(const uint32_t*)&A_[(r0+g+8)*PITCH + kb + 2*tg + 8];
            }
            uint32_t bf[4][2];
            #pragma unroll
            for (int ni=0;ni<4;ni++){
                int c0 = wn*32 + ni*8 + g;
                bf[ni][0] = *(const uint32_t*)&B_[c0*PITCH + kb + 2*tg    ];
                bf[ni][1] = *(const uint32_t*)&B_[c0*PITCH + kb + 2*tg + 8];
            }
            #pragma unroll
            for (int mi=0;mi<2;mi++)
                #pragma unroll
                for (int ni=0;ni<4;ni++)
                    MMA_F16(cc[mi][ni], a[mi], bf[ni]);
        }
        __syncthreads();
    }
    #pragma unroll
    for (int mi=0;mi<2;mi++)
        #pragma unroll
        for (int ni=0;ni<4;ni++)
            #pragma unroll
            for (int rr=0;rr<2;rr++){
                int row = wm*32 + mi*16 + g + rr*8;
                int col = wn*32 + ni*8 + 2*tg;
                float2 v = make_float2(cc[mi][ni][rr*2+0], cc[mi][ni][rr*2+1]);
                *(float2*)(g_odown + (size_t)(slot0+row)*HID + n0 + col) = v;
            }
}

// ---------------- combine ----------------------------------------------------
__global__ void k_combine(float* __restrict__ out){
    int i = blockIdx.x*blockDim.x + threadIdx.x;
    if (i >= T_TOK*HID/4) return;
    int t = i / (HID/4);
    int q = i % (HID/4);
    int s0 = g_slot_of[t*2+0], s1 = g_slot_of[t*2+1];
    float w0 = g_top_w[t*2+0], w1 = g_top_w[t*2+1];
    float4 a = *(const float4*)(g_odown + (size_t)s0*HID + q*4);
    float4 b = *(const float4*)(g_odown + (size_t)s1*HID + q*4);
    float4 o;
    o.x = w0*a.x + w1*b.x;
    o.y = w0*a.y + w1*b.y;
    o.z = w0*a.z + w1*b.z;
    o.w = w0*a.w + w1*b.w;
    *(float4*)(out + (size_t)t*HID + q*4) = o;
}

// ---------------- launch -----------------------------------------------------
extern "C" void kernel_launch(void* const* d_in, const int* in_sizes, int n_in,
                              void* d_out, int out_size){
    const float* x  = (const float*)d_in[0];
    const float* rw = (const float*)d_in[1];
    const float* wg = (const float*)d_in[2];
    const float* wu = (const float*)d_in[3];
    const float* wd = (const float*)d_in[4];
    float* out = (float*)d_out;

    __half *wgT, *wuT, *wdT;
    cudaGetSymbolAddress((void**)&wgT, g_wgT);
    cudaGetSymbolAddress((void**)&wuT, g_wuT);
    cudaGetSymbolAddress((void**)&wdT, g_wdT);

    k_init<<<(SLOT_CAP+255)/256, 256>>>();
    k_xhalf<<<(T_TOK*HID/2+255)/256, 256>>>(x);
    k_transpose<<<dim3(INTERN/32, HID/32, NEXP), dim3(32,8)>>>(wg, wgT, HID, INTERN);
    k_transpose<<<dim3(INTERN/32, HID/32, NEXP), dim3(32,8)>>>(wu, wuT, HID, INTERN);
    k_transpose<<<dim3(HID/32, INTERN/32, NEXP), dim3(32,8)>>>(wd, wdT, INTERN, HID);
    k_router<<<T_TOK/8, 256>>>(x, rw);
    k_scan<<<1, 32>>>();
    k_scatter<<<(T_TOK+255)/256, 256>>>();
    k_gemm1<<<dim3(MAXTILES, INTERN/64), 256>>>();
    k_gemm2<<<dim3(MAXTILES, HID/64), 256>>>();
    k_combine<<<(T_TOK*HID/4+255)/256, 256>>>(out);
}

// round 5
// speedup vs baseline: 2.1685x; 1.1785x over previous
#include <cuda_runtime.h>
#include <cuda_fp16.h>
#include <cstdint>

#define T_TOK 8192
#define HID   1024
#define NEXP  8
#define INTERN 2816
#define BM 128
#define BK 32                  // k halves per stage
#define MAXTILES 136
#define SLOT_CAP (MAXTILES*BM)
#define PITCH 40               // smem row pitch in halves (80B)

// ---------------- device scratch -------------------------------------------
__device__ int    g_top_idx[T_TOK*2];
__device__ float  g_top_w[T_TOK*2];
__device__ int    g_cnt[NEXP];
__device__ int    g_fill[NEXP];
__device__ int    g_slot_token[SLOT_CAP];
__device__ int    g_slot_of[T_TOK*2];
__device__ __half g_xh[(size_t)T_TOK*HID];
__device__ __half g_wgT[(size_t)NEXP*INTERN*HID];   // [e][n=I][k=H]
__device__ __half g_wuT[(size_t)NEXP*INTERN*HID];
__device__ __half g_wdT[(size_t)NEXP*HID*INTERN];   // [e][n=H][k=I]
__device__ __half g_interh[(size_t)SLOT_CAP*INTERN];
__device__ float  g_odown[(size_t)SLOT_CAP*HID];

// ---------------- helpers ----------------------------------------------------
__device__ __forceinline__ void cp16(uint32_t dst, const void* src, int sz){
    asm volatile("cp.async.cg.shared.global [%0], [%1], 16, %2;\n" :: "r"(dst), "l"(src), "r"(sz));
}
#define CP_COMMIT asm volatile("cp.async.commit_group;\n" ::: "memory")
#define CP_WAIT1  asm volatile("cp.async.wait_group 1;\n" ::: "memory")

#define MMA_F16(c,a,b) \
  asm volatile("mma.sync.aligned.m16n8k16.row.col.f32.f16.f16.f32 " \
               "{%0,%1,%2,%3},{%4,%5,%6,%7},{%8,%9},{%0,%1,%2,%3};" \
               : "+f"((c)[0]),"+f"((c)[1]),"+f"((c)[2]),"+f"((c)[3]) \
               : "r"((a)[0]),"r"((a)[1]),"r"((a)[2]),"r"((a)[3]), \
                 "r"((b)[0]),"r"((b)[1]))

#define LDSM4(r, addr) \
  asm volatile("ldmatrix.sync.aligned.m8n8.x4.shared.b16 {%0,%1,%2,%3}, [%4];" \
               : "=r"((r)[0]),"=r"((r)[1]),"=r"((r)[2]),"=r"((r)[3]) : "r"(addr))

__device__ __forceinline__ uint32_t s2u(const void* p){
    uint32_t a;
    asm("{ .reg .u64 t; cvta.to.shared.u64 t, %1; cvt.u32.u64 %0, t; }" : "=r"(a) : "l"(p));
    return a;
}

// expert/tile resolution from counts (all threads compute identically)
struct TileInfo { int e, slot0, ebase, ecnt; };
__device__ __forceinline__ TileInfo resolve_tile(int bx){
    TileInfo ti; ti.e = -1; ti.slot0 = 0; ti.ebase = 0; ti.ecnt = 0;
    int tacc = 0, base = 0;
    #pragma unroll
    for (int i=0;i<NEXP;i++){
        int c = g_cnt[i];
        int nt = (c + BM - 1) >> 7;
        if (ti.e < 0 && bx < tacc + nt){
            ti.e = i; ti.slot0 = base + (bx - tacc)*BM; ti.ebase = base; ti.ecnt = c;
        }
        tacc += nt; base += nt*BM;
    }
    return ti;
}

// ---------------- kernel 0: fused pre-pass ------------------------------------
// z<8: wg transpose, z<16: wu, z<24: wd, z==24: x->fp16 + counter init
__global__ void k_pre(const float* __restrict__ x,  const float* __restrict__ wg,
                      const float* __restrict__ wu, const float* __restrict__ wd){
    int z = blockIdx.z;
    if (z < 24){
        __shared__ float t[32][33];
        const float* src; __half* dst; int K, N, xt, yt;
        if (z < 8){       src = wg + (size_t)z*HID*INTERN;      dst = g_wgT + (size_t)z*INTERN*HID;
                          K = HID; N = INTERN; xt = blockIdx.x; yt = blockIdx.y; }
        else if (z < 16){ int e = z-8;  src = wu + (size_t)e*HID*INTERN; dst = g_wuT + (size_t)e*INTERN*HID;
                          K = HID; N = INTERN; xt = blockIdx.x; yt = blockIdx.y; }
        else {            int e = z-16; src = wd + (size_t)e*INTERN*HID; dst = g_wdT + (size_t)e*HID*INTERN;
                          K = INTERN; N = HID; xt = blockIdx.y; yt = blockIdx.x; }
        int x0 = xt*32, y0 = yt*32;
        int tx = threadIdx.x, ty = threadIdx.y;
        #pragma unroll
        for (int j=0;j<4;j++)
            t[ty+8*j][tx] = src[(size_t)(y0+ty+8*j)*N + x0+tx];
        __syncthreads();
        #pragma unroll
        for (int j=0;j<4;j++)
            dst[(size_t)(x0+ty+8*j)*K + y0+tx] = __float2half_rn(t[tx][ty+8*j]);
    } else {
        int tid = threadIdx.y*32 + threadIdx.x;
        if (blockIdx.x==0 && blockIdx.y==0 && tid<NEXP){ g_cnt[tid]=0; g_fill[tid]=0; }
        int bid = blockIdx.y*gridDim.x + blockIdx.x;       // 0..2815
        const int NH2 = T_TOK*HID/2;
        for (int i = bid*256 + tid; i < NH2; i += 2816*256){
            float2 v = ((const float2*)x)[i];
            ((__half2*)g_xh)[i] = __floats2half2_rn(v.x, v.y);
        }
    }
}

// ---------------- kernel 1: router (exact fp32) -------------------------------
__global__ void k_router(const float* __restrict__ x, const float* __restrict__ rw){
    int warp = (blockIdx.x*blockDim.x + threadIdx.x) >> 5;
    int lane = threadIdx.x & 31;
    if (warp >= T_TOK) return;
    const float* xr = x + (size_t)warp*HID;
    float acc[NEXP];
    #pragma unroll
    for (int e=0;e<NEXP;e++) acc[e]=0.f;
    for (int j=lane; j<HID; j+=32){
        float v = xr[j];
        const float* r = rw + j*NEXP;
        #pragma unroll
        for (int e=0;e<NEXP;e++) acc[e] += v*r[e];
    }
    #pragma unroll
    for (int o=16;o>0;o>>=1)
        #pragma unroll
        for (int e=0;e<NEXP;e++) acc[e] += __shfl_down_sync(0xffffffffu, acc[e], o);
    if (lane==0){
        int i0=0; float l0=acc[0];
        #pragma unroll
        for (int e=1;e<NEXP;e++) if (acc[e]>l0){ l0=acc[e]; i0=e; }
        int i1=-1; float l1=-1e30f;
        #pragma unroll
        for (int e=0;e<NEXP;e++) if (e!=i0 && acc[e]>l1){ l1=acc[e]; i1=e; }
        float w0 = 1.f/(1.f + expf(l1 - l0));
        g_top_idx[warp*2+0]=i0; g_top_idx[warp*2+1]=i1;
        g_top_w[warp*2+0]=w0;   g_top_w[warp*2+1]=1.f-w0;
        atomicAdd(&g_cnt[i0],1); atomicAdd(&g_cnt[i1],1);
    }
}

// ---------------- kernel 2: scatter (bases computed locally) ------------------
__global__ void k_scatter(){
    int t = blockIdx.x*blockDim.x + threadIdx.x;
    if (t>=T_TOK) return;
    int base[NEXP]; int b=0;
    #pragma unroll
    for (int e=0;e<NEXP;e++){ base[e]=b; b += ((g_cnt[e]+BM-1)>>7)<<7; }
    #pragma unroll
    for (int k=0;k<2;k++){
        int e = g_top_idx[t*2+k];
        int pos = atomicAdd(&g_fill[e],1);
        int slot = base[e]+pos;
        g_slot_token[slot]=t;
        g_slot_of[t*2+k]=slot;
    }
}

// ============ GEMM1: fp16 HMMA + ldmatrix, 3-stage, SwiGLU epilogue ==========
#define G1_ASTG (BM*PITCH)          // halves per A stage (5120)
#define G1_BSTG (128*PITCH)         // halves per B stage (5120)
#define G1_SMEM ((G1_ASTG+G1_BSTG)*3*2)   // 61440 bytes

__global__ void __launch_bounds__(256,2) k_gemm1(){
    extern __shared__ __half smh[];
    TileInfo ti = resolve_tile(blockIdx.x);
    if (ti.e < 0) return;
    int slot0 = ti.slot0;
    int n0 = blockIdx.y*64;
    int tid=threadIdx.x, lane=tid&31, warp=tid>>5;
    int wm = warp>>1, wn = warp&1;
    uint32_t sA = s2u(smh);                       // A stages base (bytes)
    uint32_t sB = sA + 3*G1_ASTG*2;               // B stages base

    // ldmatrix lane components
    int lAr = lane & 15,            lAk = 8*(lane>>4);            // A x4
    int lBr = (lane&7) + 8*(lane>>4), lBk = 8*((lane>>3)&1);      // B x4

    // A staging: 2 threads/row
    int arow = tid>>1, ak = (tid&1)*16;
    int vrow = (slot0 + arow - ti.ebase) < ti.ecnt;
    int tok = vrow ? g_slot_token[slot0+arow] : 0;
    const __half* asrc = g_xh + (size_t)tok*HID + ak;
    int asz = vrow ? 16 : 0;
    // B staging: 2 threads/row over 128 rows (0-63 gate, 64-127 up)
    int brow = tid>>1, bk = (tid&1)*16;
    const __half* bsrc = ((brow<64)? g_wgT + (size_t)ti.e*INTERN*HID + (size_t)(n0+brow)*HID
                                   : g_wuT + (size_t)ti.e*INTERN*HID + (size_t)(n0+brow-64)*HID) + bk;

    float cg[2][4][4], cu[2][4][4];
    #pragma unroll
    for (int i=0;i<2;i++)
        #pragma unroll
        for (int j=0;j<4;j++)
            #pragma unroll
            for (int r=0;r<4;r++){ cg[i][j][r]=0.f; cu[i][j][r]=0.f; }

    auto stage = [&](int s, int k0){
        uint32_t ad = sA + (uint32_t)(s*G1_ASTG + arow*PITCH + ak)*2;
        cp16(ad,      asrc + k0,     asz);
        cp16(ad + 16, asrc + k0 + 8, asz);
        uint32_t bd = sB + (uint32_t)(s*G1_BSTG + brow*PITCH + bk)*2;
        cp16(bd,      bsrc + k0,     16);
        cp16(bd + 16, bsrc + k0 + 8, 16);
        CP_COMMIT;
    };

    stage(0, 0); stage(1, BK);
    const int NT = HID/BK;   // 32
    for (int kt=0; kt<NT; kt++){
        int s = kt % 3;
        CP_WAIT1;
        __syncthreads();
        if (kt+2 < NT) stage((kt+2)%3, (kt+2)*BK);
        uint32_t aoff = sA + (uint32_t)(s*G1_ASTG)*2;
        uint32_t boff = sB + (uint32_t)(s*G1_BSTG)*2;
        #pragma unroll
        for (int ks=0; ks<2; ks++){
            int kb = ks*16;
            uint32_t a0[4], a1[4];
            LDSM4(a0, aoff + (uint32_t)((wm*32     + lAr)*PITCH + kb + lAk)*2);
            LDSM4(a1, aoff + (uint32_t)((wm*32 +16 + lAr)*PITCH + kb + lAk)*2);
            #pragma unroll
            for (int nq=0;nq<2;nq++){
                int c0 = wn*32 + nq*16;
                uint32_t bg[4], bu[4];
                LDSM4(bg, boff + (uint32_t)((c0    + lBr)*PITCH + kb + lBk)*2);
                LDSM4(bu, boff + (uint32_t)((c0+64 + lBr)*PITCH + kb + lBk)*2);
                MMA_F16(cg[0][nq*2+0], a0, bg+0);
                MMA_F16(cg[0][nq*2+1], a0, bg+2);
                MMA_F16(cg[1][nq*2+0], a1, bg+0);
                MMA_F16(cg[1][nq*2+1], a1, bg+2);
                MMA_F16(cu[0][nq*2+0], a0, bu+0);
                MMA_F16(cu[0][nq*2+1], a0, bu+2);
                MMA_F16(cu[1][nq*2+0], a1, bu+0);
                MMA_F16(cu[1][nq*2+1], a1, bu+2);
            }
        }
    }
    // SwiGLU epilogue -> g_interh
    int g8 = lane>>2, tg = lane&3;
    #pragma unroll
    for (int mi=0;mi<2;mi++)
        #pragma unroll
        for (int ni=0;ni<4;ni++)
            #pragma unroll
            for (int rr=0;rr<2;rr++){
                int row = wm*32 + mi*16 + g8 + rr*8;
                int col = wn*32 + ni*8 + 2*tg;
                float g0 = cg[mi][ni][rr*2+0], u0 = cu[mi][ni][rr*2+0];
                float g1 = cg[mi][ni][rr*2+1], u1 = cu[mi][ni][rr*2+1];
                float v0 = u0 * (g0 / (1.f + expf(-g0)));
                float v1 = u1 * (g1 / (1.f + expf(-g1)));
                *(__half2*)(g_interh + (size_t)(slot0+row)*INTERN + n0 + col)
                    = __floats2half2_rn(v0, v1);
            }
}

// ============ GEMM2: fp16 HMMA + ldmatrix, 3-stage ===========================
#define G2_ASTG (BM*PITCH)          // 5120 halves
#define G2_BSTG (64*PITCH)          // 2560 halves
#define G2_SMEM ((G2_ASTG+G2_BSTG)*3*2)   // 46080 bytes

__global__ void __launch_bounds__(256,2) k_gemm2(){
    extern __shared__ __half smh[];
    TileInfo ti = resolve_tile(blockIdx.x);
    if (ti.e < 0) return;
    int slot0 = ti.slot0;
    int n0 = blockIdx.y*64;
    int tid=threadIdx.x, lane=tid&31, warp=tid>>5;
    int wm = warp>>1, wn = warp&1;
    uint32_t sA = s2u(smh);
    uint32_t sB = sA + 3*G2_ASTG*2;

    int lAr = lane & 15,              lAk = 8*(lane>>4);
    int lBr = (lane&7) + 8*(lane>>4), lBk = 8*((lane>>3)&1);

    int arow = tid>>1, ak = (tid&1)*16;
    const __half* asrc = g_interh + (size_t)(slot0+arow)*INTERN + ak;
    int brow = tid>>2, bk = (tid&3)*8;
    const __half* bsrc = g_wdT + (size_t)ti.e*HID*INTERN + (size_t)(n0+brow)*INTERN + bk;

    float cc[2][4][4];
    #pragma unroll
    for (int i=0;i<2;i++)
        #pragma unroll
        for (int j=0;j<4;j++)
            #pragma unroll
            for (int r=0;r<4;r++) cc[i][j][r]=0.f;

    auto stage = [&](int s, int k0){
        uint32_t ad = sA + (uint32_t)(s*G2_ASTG + arow*PITCH + ak)*2;
        cp16(ad,      asrc + k0,     16);
        cp16(ad + 16, asrc + k0 + 8, 16);
        uint32_t bd = sB + (uint32_t)(s*G2_BSTG + brow*PITCH + bk)*2;
        cp16(bd, bsrc + k0, 16);
        CP_COMMIT;
    };

    stage(0, 0); stage(1, BK);
    const int NT = INTERN/BK;   // 88
    for (int kt=0; kt<NT; kt++){
        int s = kt % 3;
        CP_WAIT1;
        __syncthreads();
        if (kt+2 < NT) stage((kt+2)%3, (kt+2)*BK);
        uint32_t aoff = sA + (uint32_t)(s*G2_ASTG)*2;
        uint32_t boff = sB + (uint32_t)(s*G2_BSTG)*2;
        #pragma unroll
        for (int ks=0; ks<2; ks++){
            int kb = ks*16;
            uint32_t a0[4], a1[4];
            LDSM4(a0, aoff + (uint32_t)((wm*32     + lAr)*PITCH + kb + lAk)*2);
            LDSM4(a1, aoff + (uint32_t)((wm*32 +16 + lAr)*PITCH + kb + lAk)*2);
            #pragma unroll
            for (int nq=0;nq<2;nq++){
                int c0 = wn*32 + nq*16;
                uint32_t bf[4];
                LDSM4(bf, boff + (uint32_t)((c0 + lBr)*PITCH + kb + lBk)*2);
                MMA_F16(cc[0][nq*2+0], a0, bf+0);
                MMA_F16(cc[0][nq*2+1], a0, bf+2);
                MMA_F16(cc[1][nq*2+0], a1, bf+0);
                MMA_F16(cc[1][nq*2+1], a1, bf+2);
            }
        }
    }
    int g8 = lane>>2, tg = lane&3;
    #pragma unroll
    for (int mi=0;mi<2;mi++)
        #pragma unroll
        for (int ni=0;ni<4;ni++)
            #pragma unroll
            for (int rr=0;rr<2;rr++){
                int row = wm*32 + mi*16 + g8 + rr*8;
                int col = wn*32 + ni*8 + 2*tg;
                float2 v = make_float2(cc[mi][ni][rr*2+0], cc[mi][ni][rr*2+1]);
                *(float2*)(g_odown + (size_t)(slot0+row)*HID + n0 + col) = v;
            }
}

// ---------------- combine ----------------------------------------------------
__global__ void k_combine(float* __restrict__ out){
    int i = blockIdx.x*blockDim.x + threadIdx.x;
    if (i >= T_TOK*HID/4) return;
    int t = i / (HID/4);
    int q = i % (HID/4);
    int s0 = g_slot_of[t*2+0], s1 = g_slot_of[t*2+1];
    float w0 = g_top_w[t*2+0], w1 = g_top_w[t*2+1];
    float4 a = *(const float4*)(g_odown + (size_t)s0*HID + q*4);
    float4 b = *(const float4*)(g_odown + (size_t)s1*HID + q*4);
    float4 o;
    o.x = w0*a.x + w1*b.x;
    o.y = w0*a.y + w1*b.y;
    o.z = w0*a.z + w1*b.z;
    o.w = w0*a.w + w1*b.w;
    *(float4*)(out + (size_t)t*HID + q*4) = o;
}

// ---------------- launch -----------------------------------------------------
extern "C" void kernel_launch(void* const* d_in, const int* in_sizes, int n_in,
                              void* d_out, int out_size){
    const float* x  = (const float*)d_in[0];
    const float* rw = (const float*)d_in[1];
    const float* wg = (const float*)d_in[2];
    const float* wu = (const float*)d_in[3];
    const float* wd = (const float*)d_in[4];
    float* out = (float*)d_out;

    cudaFuncSetAttribute(k_gemm1, cudaFuncAttributeMaxDynamicSharedMemorySize, G1_SMEM);
    cudaFuncSetAttribute(k_gemm2, cudaFuncAttributeMaxDynamicSharedMemorySize, G2_SMEM);

    k_pre<<<dim3(INTERN/32, HID/32, 25), dim3(32,8)>>>(x, wg, wu, wd);
    k_router<<<T_TOK/8, 256>>>(x, rw);
    k_scatter<<<(T_TOK+255)/256, 256>>>();
    k_gemm1<<<dim3(MAXTILES, INTERN/64), 256, G1_SMEM>>>();
    k_gemm2<<<dim3(MAXTILES, HID/64), 256, G2_SMEM>>>();
    k_combine<<<(T_TOK*HID/4+255)/256, 256>>>(out);
}